// round 10
// baseline (speedup 1.0000x reference)
#include <cuda_runtime.h>

// SobelLoss: loss = sum_{voxels,d in {x,y,z}} |conv_d(moved - label)| / (3*N)
// Shapes: (B=2, 1, D=160, H=192, W=160) fp32, zero padding.
// Sobel separable: S=[1,2,1] smooth, D=[-1,0,1] derivative.
// This version: 128-thread CTAs at 16 CTAs/SM (32 regs, 64 warps/SM, ONE wave),
// ZCHUNK=16, NBUF=3 single-plane prefetch, 36-wide 8B-aligned tile,
// packed f32x2 math on (even,odd) row pairs.

typedef unsigned long long ull;

#define DIMX 160
#define DIMY 192
#define DIMZ 160
#define NBATCH 2
#define PLANE (DIMY * DIMX)

#define TX 32
#define TY 4
#define NT (TX * TY)            // 128
#define OY 8                    // output rows per block (2 per thread)
#define ZCHUNK 16
#define NZCH (DIMZ / ZCHUNK)    // 10

#define TILE_W 36               // raw cols: gx in [32bx-2, 32bx+33] (8B aligned)
#define NPAIR 5                 // 10 raw rows as 5 (even,odd) pairs
#define PLANE_ULL (NPAIR * TILE_W)     // 180 ull per plane buffer
#define NSLOT (NPAIR * (TILE_W / 2))   // 90 fetch slots (col pairs)
#define NBUF 3

#define GRID_X (DIMX / TX)      // 5
#define GRID_Y (DIMY / OY)      // 24
#define TOTAL_CTAS (GRID_X * GRID_Y * NBATCH * NZCH)   // 2400

// 1 / (3 * B*D*H*W) = 1 / 29491200
#define SCALE 3.3908420632258286e-08f

__device__ float    g_acc = 0.0f;
__device__ unsigned g_cnt = 0;

// ---- packed f32x2 helpers (Blackwell sm_103a) ----
__device__ __forceinline__ ull pk(float lo, float hi) {
    ull r; asm("mov.b64 %0, {%1, %2};" : "=l"(r) : "f"(lo), "f"(hi)); return r;
}
__device__ __forceinline__ void upk(ull p, float& lo, float& hi) {
    asm("mov.b64 {%0, %1}, %2;" : "=f"(lo), "=f"(hi) : "l"(p));
}
__device__ __forceinline__ ull padd(ull a, ull b) {
    ull r; asm("add.rn.f32x2 %0, %1, %2;" : "=l"(r) : "l"(a), "l"(b)); return r;
}
__device__ __forceinline__ ull pfma(ull a, ull b, ull c) {   // a*b + c
    ull r; asm("fma.rn.f32x2 %0, %1, %2, %3;" : "=l"(r) : "l"(a), "l"(b), "l"(c)); return r;
}
// (hi(a), lo(b))
__device__ __forceinline__ ull pmid(ull a, ull b) {
    float alo, ahi, blo, bhi;
    upk(a, alo, ahi); upk(b, blo, bhi);
    return pk(ahi, blo);
}

__launch_bounds__(NT, 16)   // force <=32 regs -> 16 CTAs/SM -> 2400 grid = ONE wave
__global__ void sobel_loss_kernel(const float* __restrict__ moved,
                                  const float* __restrict__ label,
                                  float* __restrict__ out)
{
    // plane buffer: [pair][col] = float2{ raw row 2*pair, raw row 2*pair+1 }
    __shared__ __align__(16) ull tile2[NBUF][PLANE_ULL];

    const int tx  = threadIdx.x;
    const int ty  = threadIdx.y;
    const int tid = ty * TX + tx;

    const int b  = blockIdx.z / NZCH;
    const int z0 = (blockIdx.z % NZCH) * ZCHUNK;

    const int gy0  = blockIdx.y * OY - 1;     // global y of tile row 0
    const int gxv0 = blockIdx.x * TX - 2;     // global x of tile col 0 (even -> 8B aligned)

    const float* mb = moved + (size_t)b * DIMZ * PLANE;
    const float* lb = label + (size_t)b * DIMZ * PLANE;

    const ull C2  = pk(2.0f, 2.0f);
    const ull CM1 = pk(-1.0f, -1.0f);

    // ---- fetch slot: (row pair, col pair) -> 2 rows x 2 cols per thread ----
    const int pair = tid / (TILE_W / 2);        // 0..4 (tid < 90)
    const int vc2  = tid - pair * (TILE_W / 2); // 0..17
    const int gx   = gxv0 + 2 * vc2;            // even, 8B aligned; pair fully in/out
    const int gyE  = gy0 + 2 * pair;
    const bool slotok = (tid < NSLOT) && ((unsigned)gx < (unsigned)DIMX);
    const int offE = (slotok && (unsigned)gyE       < (unsigned)DIMY) ? (gyE * DIMX + gx)       : -1;
    const int offO = (slotok && (unsigned)(gyE + 1) < (unsigned)DIMY) ? ((gyE + 1) * DIMX + gx) : -1;
    const int wOff = pair * TILE_W + 2 * vc2;   // ull index; 16B aligned (even)

    ull pre0, pre1;   // single-plane prefetch registers

    auto fetch = [&](int z) {
        ull mE = 0, lE = 0, mO = 0, lO = 0;
        if ((unsigned)z < (unsigned)DIMZ) {
            const float* mz = mb + (size_t)z * PLANE;
            const float* lz = lb + (size_t)z * PLANE;
            if (offE >= 0) { mE = *(const ull*)(mz + offE); lE = *(const ull*)(lz + offE); }
            if (offO >= 0) { mO = *(const ull*)(mz + offO); lO = *(const ull*)(lz + offO); }
        }
        ull vE = pfma(lE, CM1, mE);   // moved - label, even row (2 cols)
        ull vO = pfma(lO, CM1, mO);   // odd row
        float e0, e1, o0, o1;
        upk(vE, e0, e1); upk(vO, o0, o1);
        pre0 = pk(e0, o0);            // column L: (even,odd)
        pre1 = pk(e1, o1);            // column R: (even,odd)
    };

    auto store = [&](int buf) {
        if (tid < NSLOT)
            *(ulonglong2*)&tile2[buf][wOff] = make_ulonglong2(pre0, pre1);
    };

    // ---- packed in-plane partials for this thread's output-row pair ----
    // output col tx (global 32bx+tx) -> raw cols tx+1..tx+3 (local)
    auto compute_pqr = [&](int buf, ull& pP, ull& qP, ull& rP) {
        const ull* b0 = &tile2[buf][ty * TILE_W + tx + 1];
        ull a0 = b0[0],          c0 = b0[1],          e0 = b0[2];
        ull a1 = b0[TILE_W],     c1 = b0[TILE_W + 1], e1 = b0[TILE_W + 2];
        ull s0 = padd(pfma(c0, C2, a0), e0);
        ull d0 = pfma(a0, CM1, e0);
        ull s1 = padd(pfma(c1, C2, a1), e1);
        ull d1 = pfma(a1, CM1, e1);
        qP = pfma(s0, CM1, s1);
        rP = padd(pfma(pmid(s0, s1), C2, s0), s1);
        pP = padd(pfma(pmid(d0, d1), C2, d0), d1);
    };

    float acc = 0.0f;
    ull pP0, qP0, rP0, pP1, qP1, rP1;

    // ---- prologue: planes z0-1, z0, z0+1 -> buf (plane mod 3) ----
    fetch(z0 - 1); store((z0 + 2) % NBUF);   // z0-1 == z0+2 (mod 3)
    fetch(z0);     store( z0      % NBUF);
    fetch(z0 + 1); store((z0 + 1) % NBUF);
    __syncthreads();

    compute_pqr((z0 + 2) % NBUF, pP0, qP0, rP0);   // plane z0-1
    compute_pqr( z0      % NBUF, pP1, qP1, rP1);   // plane z0

    fetch(z0 + 2);   // prefetch: at iter k, registers hold plane z0+k+1

    int cBuf = (z0 + 1) % NBUF;   // buffer of compute plane z = z0+k
    int sBuf = (z0 + 2) % NBUF;   // store target (z+1) mod 3

    // ---- main loop: iter k (z=z0+k): barrier; store plane z+1 (over z-2);
    //      fetch plane z+2; compute pqr(plane z); emit output plane z-1 ----
    #pragma unroll 4
    for (int k = 1; k <= ZCHUNK; ++k) {
        const int z = z0 + k;
        __syncthreads();                     // all compute(z-1) done everywhere
        if (k < ZCHUNK) {
            store(sBuf);                     // plane z+1 over plane z-2 (1 barrier back ok: WAR)
            if (k + 2 <= ZCHUNK) fetch(z + 2);
        }

        ull pP2, qP2, rP2;
        compute_pqr(cBuf, pP2, qP2, rP2);    // plane z

        ull Gx = padd(pfma(pP1, C2, pP0), pP2);
        ull Gy = padd(pfma(qP1, C2, qP0), qP2);
        ull Gz = pfma(rP0, CM1, rP2);

        float gxa, gxb, gya, gyb, gza, gzb;
        upk(Gx, gxa, gxb); upk(Gy, gya, gyb); upk(Gz, gza, gzb);
        acc += fabsf(gxa) + fabsf(gya);
        acc += fabsf(gza) + fabsf(gxb);
        acc += fabsf(gyb) + fabsf(gzb);

        pP0 = pP1; pP1 = pP2;
        qP0 = qP1; qP1 = qP2;
        rP0 = rP1; rP1 = rP2;
        cBuf = (cBuf == NBUF - 1) ? 0 : cBuf + 1;
        sBuf = (sBuf == NBUF - 1) ? 0 : sBuf + 1;
    }

    // ---- block reduction ----
    #pragma unroll
    for (int o = 16; o > 0; o >>= 1)
        acc += __shfl_down_sync(0xFFFFFFFFu, acc, o);

    __shared__ float wsum[NT / 32];
    if ((tid & 31) == 0) wsum[tid >> 5] = acc;
    __syncthreads();

    if (tid < (NT / 32)) {
        float v = wsum[tid];
        #pragma unroll
        for (int o = (NT / 64); o > 0; o >>= 1)
            v += __shfl_down_sync(0xFFu, v, o);
        if (tid == 0) {
            atomicAdd(&g_acc, v);
            __threadfence();
            if (atomicAdd(&g_cnt, 1u) == TOTAL_CTAS - 1) {
                __threadfence();
                *out = g_acc * SCALE;
                g_acc = 0.0f;      // reset for next (graph-replayed) launch
                g_cnt = 0;
            }
        }
    }
}

extern "C" void kernel_launch(void* const* d_in, const int* in_sizes, int n_in,
                              void* d_out, int out_size)
{
    const float* moved = (const float*)d_in[0];
    const float* label = (const float*)d_in[1];
    float* out = (float*)d_out;

    dim3 grid(GRID_X, GRID_Y, NBATCH * NZCH);   // (5, 24, 20) = 2400 CTAs
    dim3 block(TX, TY);                         // (32, 4)
    sobel_loss_kernel<<<grid, block>>>(moved, label, out);
}

// round 11
// speedup vs baseline: 1.0755x; 1.0755x over previous
#include <cuda_runtime.h>

// SobelLoss: loss = sum_{voxels,d in {x,y,z}} |conv_d(moved - label)| / (3*N)
// Shapes: (B=2, 1, D=160, H=192, W=160) fp32, zero padding.
// Sobel separable: S=[1,2,1] smooth, D=[-1,0,1] derivative.
// This version: 128 threads/CTA, 4 outputs/thread (2 cols x 2 rows),
// 40-wide tile with float4 global loads, vectorized LDS (128b), packed f32x2
// math + packed abs-accumulate, NBUF=3 rolling pipeline, 1200 CTAs @ 8/SM.

typedef unsigned long long ull;

#define DIMX 160
#define DIMY 192
#define DIMZ 160
#define NBATCH 2
#define PLANE (DIMY * DIMX)

#define TXH 16                  // threads x (each does 2 output cols)
#define TY 8                    // threads y (each does 2 output rows)
#define NT (TXH * TY)           // 128
#define OX 32                   // output cols per CTA
#define OY 16                   // output rows per CTA
#define ZCHUNK 16
#define NZCH (DIMZ / ZCHUNK)    // 10

#define TILE_W 40               // raw cols: gx in [32bx-4, 32bx+35], 16B aligned
#define NPAIR 9                 // 18 raw rows as 9 (even,odd) pairs
#define PLANE_ULL (NPAIR * TILE_W)   // 360 ull per plane buffer
#define NQ 10                   // col quads per pair-row
#define NSLOT (NPAIR * NQ)      // 90 fetch slots
#define NBUF 3

#define GRID_X (DIMX / OX)      // 5
#define GRID_Y (DIMY / OY)      // 12
#define TOTAL_CTAS (GRID_X * GRID_Y * NBATCH * NZCH)   // 1200

// 1 / (3 * B*D*H*W) = 1 / 29491200
#define SCALE 3.3908420632258286e-08f
#define ABSM 0x7FFFFFFF7FFFFFFFULL

__device__ float    g_acc = 0.0f;
__device__ unsigned g_cnt = 0;

// ---- packed f32x2 helpers (Blackwell sm_103a) ----
__device__ __forceinline__ ull pk(float lo, float hi) {
    ull r; asm("mov.b64 %0, {%1, %2};" : "=l"(r) : "f"(lo), "f"(hi)); return r;
}
__device__ __forceinline__ void upk(ull p, float& lo, float& hi) {
    asm("mov.b64 {%0, %1}, %2;" : "=f"(lo), "=f"(hi) : "l"(p));
}
__device__ __forceinline__ ull padd(ull a, ull b) {
    ull r; asm("add.rn.f32x2 %0, %1, %2;" : "=l"(r) : "l"(a), "l"(b)); return r;
}
__device__ __forceinline__ ull pfma(ull a, ull b, ull c) {   // a*b + c
    ull r; asm("fma.rn.f32x2 %0, %1, %2, %3;" : "=l"(r) : "l"(a), "l"(b), "l"(c)); return r;
}
// (hi(a), lo(b))
__device__ __forceinline__ ull pmid(ull a, ull b) {
    float alo, ahi, blo, bhi;
    upk(a, alo, ahi); upk(b, blo, bhi);
    return pk(ahi, blo);
}

__launch_bounds__(NT, 8)   // <=64 regs -> 8 CTAs/SM -> 1200 grid = ONE wave
__global__ void sobel_loss_kernel(const float* __restrict__ moved,
                                  const float* __restrict__ label,
                                  float* __restrict__ out)
{
    // plane buffer: ull[pair][rawcol] = float2{ raw row 2*pair, raw row 2*pair+1 }
    __shared__ __align__(16) ull tile2[NBUF][PLANE_ULL];

    const int txh = threadIdx.x;        // 0..15
    const int ty  = threadIdx.y;        // 0..7
    const int tid = ty * TXH + txh;

    const int b  = blockIdx.z / NZCH;
    const int z0 = (blockIdx.z % NZCH) * ZCHUNK;

    const int gy0 = blockIdx.y * OY - 1;   // global y of raw row 0
    const int gx0 = blockIdx.x * OX - 4;   // global x of raw col 0 (mult of 4)

    const float* mb = moved + (size_t)b * DIMZ * PLANE;
    const float* lb = label + (size_t)b * DIMZ * PLANE;

    const ull C2  = pk(2.0f, 2.0f);
    const ull CM1 = pk(-1.0f, -1.0f);

    // ---- fetch slot: (row pair, col quad) -> 2 rows x 4 cols per thread ----
    const int pair = tid / NQ;                  // 0..8 (tid < 90)
    const int q    = tid - pair * NQ;           // 0..9
    const int gx   = gx0 + 4 * q;               // mult of 4; quad fully in/out
    const int gyE  = gy0 + 2 * pair;
    const bool okx = (tid < NSLOT) && ((unsigned)gx < (unsigned)DIMX);
    const int offE = (okx && (unsigned)gyE       < (unsigned)DIMY) ? (gyE * DIMX + gx)       : -1;
    const int offO = (okx && (unsigned)(gyE + 1) < (unsigned)DIMY) ? ((gyE + 1) * DIMX + gx) : -1;
    const int wOff = pair * TILE_W + 4 * q;     // ull index; 32B aligned

    ull pr0, pr1, pr2, pr3;   // prefetched pair-packed diffs (4 cols)

    auto fetch = [&](int z) {
        float4 vE = make_float4(0.f, 0.f, 0.f, 0.f), vO = vE;
        if ((unsigned)z < (unsigned)DIMZ) {
            const float* mz = mb + (size_t)z * PLANE;
            const float* lz = lb + (size_t)z * PLANE;
            if (offE >= 0) {
                float4 m = *(const float4*)(mz + offE);
                float4 l = *(const float4*)(lz + offE);
                vE = make_float4(m.x - l.x, m.y - l.y, m.z - l.z, m.w - l.w);
            }
            if (offO >= 0) {
                float4 m = *(const float4*)(mz + offO);
                float4 l = *(const float4*)(lz + offO);
                vO = make_float4(m.x - l.x, m.y - l.y, m.z - l.z, m.w - l.w);
            }
        }
        pr0 = pk(vE.x, vO.x); pr1 = pk(vE.y, vO.y);
        pr2 = pk(vE.z, vO.z); pr3 = pk(vE.w, vO.w);
    };

    auto store = [&](int buf) {
        if (tid < NSLOT) {
            *(ulonglong2*)&tile2[buf][wOff]     = make_ulonglong2(pr0, pr1);
            *(ulonglong2*)&tile2[buf][wOff + 2] = make_ulonglong2(pr2, pr3);
        }
    };

    // ---- per-plane partials for 2 output cols (A: 2txh, B: 2txh+1) x row pair ----
    // output col j -> raw cols j+3..j+5; col A needs raw cb+1..cb+3, B: cb+2..cb+4
    const int cb = 2 * txh + 2;   // 16B-aligned ull base (raw col 2txh+2)

    auto compute = [&](int buf,
                       ull& pA, ull& qA, ull& rA,
                       ull& pB, ull& qB, ull& rB) {
        const ull* bp0 = &tile2[buf][ ty      * TILE_W + cb];
        const ull* bp1 = &tile2[buf][(ty + 1) * TILE_W + cb];
        ulonglong2 u00 = *(const ulonglong2*)(bp0);      // cols cb, cb+1
        ulonglong2 u01 = *(const ulonglong2*)(bp0 + 2);  // cols cb+2, cb+3
        ull        f0v = bp0[4];                         // col  cb+4
        ulonglong2 u10 = *(const ulonglong2*)(bp1);
        ulonglong2 u11 = *(const ulonglong2*)(bp1 + 2);
        ull        f1v = bp1[4];

        ull a0 = u00.y, b0 = u01.x, e0 = u01.y;   // row pair ty
        ull a1 = u10.y, b1 = u11.x, e1 = u11.y;   // row pair ty+1

        ull sA0 = padd(pfma(b0, C2, a0), e0);     // Sx col A, pair0
        ull sB0 = padd(pfma(e0, C2, b0), f0v);    // Sx col B, pair0
        ull dA0 = pfma(a0, CM1, e0);              // Dx col A, pair0
        ull dB0 = pfma(b0, CM1, f0v);
        ull sA1 = padd(pfma(b1, C2, a1), e1);
        ull sB1 = padd(pfma(e1, C2, b1), f1v);
        ull dA1 = pfma(a1, CM1, e1);
        ull dB1 = pfma(b1, CM1, f1v);

        qA = pfma(sA0, CM1, sA1);
        rA = padd(pfma(pmid(sA0, sA1), C2, sA0), sA1);
        pA = padd(pfma(pmid(dA0, dA1), C2, dA0), dA1);
        qB = pfma(sB0, CM1, sB1);
        rB = padd(pfma(pmid(sB0, sB1), C2, sB0), sB1);
        pB = padd(pfma(pmid(dB0, dB1), C2, dB0), dB1);
    };

    // ---- prologue: planes z0-1, z0, z0+1 -> buf (plane mod 3) ----
    fetch(z0 - 1); store((z0 + 2) % NBUF);
    fetch(z0);     store( z0      % NBUF);
    fetch(z0 + 1); store((z0 + 1) % NBUF);
    __syncthreads();

    ull pA0,qA0,rA0, pA1,qA1,rA1, pB0,qB0,rB0, pB1,qB1,rB1;
    compute((z0 + 2) % NBUF, pA0,qA0,rA0, pB0,qB0,rB0);   // plane z0-1
    compute( z0      % NBUF, pA1,qA1,rA1, pB1,qB1,rB1);   // plane z0

    fetch(z0 + 2);   // at iter k, prefetch regs hold plane z0+k+1

    ull accA = 0, accB = 0;
    int cBuf = (z0 + 1) % NBUF;   // buffer of compute plane z = z0+k
    int sBuf = (z0 + 2) % NBUF;   // store target (z+1) mod 3

    #pragma unroll 2
    for (int k = 1; k <= ZCHUNK; ++k) {
        __syncthreads();                     // all compute(z-1) done everywhere
        if (k < ZCHUNK) {
            store(sBuf);                     // plane z+1 over plane z-2 (WAR, 1 barrier ok)
            if (k + 2 <= ZCHUNK) fetch(z0 + k + 2);
        }

        ull pA2,qA2,rA2, pB2,qB2,rB2;
        compute(cBuf, pA2,qA2,rA2, pB2,qB2,rB2);   // plane z

        ull GxA = padd(pfma(pA1, C2, pA0), pA2);
        ull GxB = padd(pfma(pB1, C2, pB0), pB2);
        ull GyA = padd(pfma(qA1, C2, qA0), qA2);
        ull GyB = padd(pfma(qB1, C2, qB0), qB2);
        ull GzA = pfma(rA0, CM1, rA2);
        ull GzB = pfma(rB0, CM1, rB2);

        accA = padd(accA, GxA & ABSM);
        accB = padd(accB, GxB & ABSM);
        accA = padd(accA, GyA & ABSM);
        accB = padd(accB, GyB & ABSM);
        accA = padd(accA, GzA & ABSM);
        accB = padd(accB, GzB & ABSM);

        pA0 = pA1; pA1 = pA2; qA0 = qA1; qA1 = qA2; rA0 = rA1; rA1 = rA2;
        pB0 = pB1; pB1 = pB2; qB0 = qB1; qB1 = qB2; rB0 = rB1; rB1 = rB2;
        cBuf = (cBuf == NBUF - 1) ? 0 : cBuf + 1;
        sBuf = (sBuf == NBUF - 1) ? 0 : sBuf + 1;
    }

    // ---- reduce packed accumulators ----
    accA = padd(accA, accB);
    float lo, hi;
    upk(accA, lo, hi);
    float acc = lo + hi;

    #pragma unroll
    for (int o = 16; o > 0; o >>= 1)
        acc += __shfl_down_sync(0xFFFFFFFFu, acc, o);

    __shared__ float wsum[NT / 32];
    if ((tid & 31) == 0) wsum[tid >> 5] = acc;
    __syncthreads();

    if (tid < (NT / 32)) {
        float v = wsum[tid];
        #pragma unroll
        for (int o = (NT / 64); o > 0; o >>= 1)
            v += __shfl_down_sync(0xFFu, v, o);
        if (tid == 0) {
            atomicAdd(&g_acc, v);
            __threadfence();
            if (atomicAdd(&g_cnt, 1u) == TOTAL_CTAS - 1) {
                __threadfence();
                *out = g_acc * SCALE;
                g_acc = 0.0f;      // reset for next (graph-replayed) launch
                g_cnt = 0;
            }
        }
    }
}

extern "C" void kernel_launch(void* const* d_in, const int* in_sizes, int n_in,
                              void* d_out, int out_size)
{
    const float* moved = (const float*)d_in[0];
    const float* label = (const float*)d_in[1];
    float* out = (float*)d_out;

    dim3 grid(GRID_X, GRID_Y, NBATCH * NZCH);   // (5, 12, 20) = 1200 CTAs
    dim3 block(TXH, TY);                        // (16, 8)
    sobel_loss_kernel<<<grid, block>>>(moved, label, out);
}